// round 14
// baseline (speedup 1.0000x reference)
#include <cuda_runtime.h>
#include <math.h>

#define NB 32
#define NS 1024
#define ND 256
#define NDS 64
#define NM 3
#define TS 128   // timesteps per out_kernel block

typedef unsigned long long ull;

// ---------------- scratch (device globals; no cudaMalloc allowed) ----------
__device__ float g_xp[(size_t)NB * NS * NM * NDS];   // [B][S][M*DS]  (XW@x + Xb + Hb)
__device__ float g_hn[(size_t)NB * NS * NM * NDS];   // [B][S][M*DS]  (h_new per step)

// ---------------- packed f32x2 helpers -------------------------------------
__device__ __forceinline__ void fma2(ull& acc, ull a, ull b) {
    asm("fma.rn.f32x2 %0, %1, %2, %0;" : "+l"(acc) : "l"(a), "l"(b));
}
__device__ __forceinline__ ull pack2(float x, float y) {
    ull r; asm("mov.b64 %0, {%1, %2};" : "=l"(r) : "f"(x), "f"(y)); return r;
}
__device__ __forceinline__ float2 unpack2(ull v) {
    float2 r; asm("mov.b64 {%0, %1}, %2;" : "=f"(r.x), "=f"(r.y) : "l"(v)); return r;
}
__device__ __forceinline__ float sum2(ull v) { float2 f = unpack2(v); return f.x + f.y; }

__device__ __forceinline__ float tanh_fast(float x) {
    float y; asm("tanh.approx.f32 %0, %1;" : "=f"(y) : "f"(x)); return y;
}

// ---------------- cp.async helpers ------------------------------------------
__device__ __forceinline__ void cp_async16(void* smem_dst, const void* gsrc) {
    unsigned s = (unsigned)__cvta_generic_to_shared(smem_dst);
    asm volatile("cp.async.ca.shared.global [%0], [%1], 16;" :: "r"(s), "l"(gsrc));
}
__device__ __forceinline__ void cp_commit() { asm volatile("cp.async.commit_group;"); }
__device__ __forceinline__ void cp_wait1()  { asm volatile("cp.async.wait_group 1;"); }

// ======================= Kernel 1: xp = XW@x + Xb + Hb =====================
__global__ void __launch_bounds__(256) xproj_kernel(
    const float* __restrict__ xa, const float* __restrict__ xv, const float* __restrict__ xl,
    const float* __restrict__ XW, const float* __restrict__ Xb, const float* __restrict__ Hb)
{
    __shared__ __align__(16) float Xs[64][64];   // [t][k]
    __shared__ __align__(16) float Wt[64][64];   // [k][d] (XW transposed)

    const int m  = blockIdx.z;
    const int bb = blockIdx.y;
    const int t0 = blockIdx.x * 64;
    const float* xm = (m == 0) ? xa : ((m == 1) ? xv : xl);

    const int tid = threadIdx.x;
    const int tx = tid & 15, ty = tid >> 4;

    ull acc[4][2] = {};

    const int ldx_row = tid >> 2, ldx_q = tid & 3;
    const int ldw_d = tid & 63, ldw_g = tid >> 6;

    for (int kc = 0; kc < 4; kc++) {
        __syncthreads();
        #pragma unroll
        for (int g = 0; g < 4; g++) {
            int col = ldx_q * 16 + g * 4;
            float4 v = *(const float4*)&xm[((size_t)(bb * NS) + t0 + ldx_row) * ND + kc * 64 + col];
            *(float4*)&Xs[ldx_row][col] = v;
        }
        #pragma unroll
        for (int g = 0; g < 4; g++) {
            int kk = ldw_g * 16 + g * 4;
            float4 w = *(const float4*)&XW[((size_t)(m * NDS + ldw_d)) * ND + kc * 64 + kk];
            Wt[kk + 0][ldw_d] = w.x; Wt[kk + 1][ldw_d] = w.y;
            Wt[kk + 2][ldw_d] = w.z; Wt[kk + 3][ldw_d] = w.w;
        }
        __syncthreads();
        #pragma unroll 4
        for (int kq = 0; kq < 16; kq++) {
            float4 av[4];
            #pragma unroll
            for (int i = 0; i < 4; i++)
                av[i] = *(const float4*)&Xs[ty + 16 * i][4 * kq];
            #pragma unroll
            for (int q = 0; q < 4; q++) {
                const int kk = 4 * kq + q;
                ull bv0 = *(const ull*)&Wt[kk][2 * tx];
                ull bv1 = *(const ull*)&Wt[kk][2 * tx + 32];
                #pragma unroll
                for (int i = 0; i < 4; i++) {
                    float a = (q == 0) ? av[i].x : (q == 1) ? av[i].y
                            : (q == 2) ? av[i].z : av[i].w;
                    ull aa = pack2(a, a);
                    fma2(acc[i][0], aa, bv0);
                    fma2(acc[i][1], aa, bv1);
                }
            }
        }
    }
    #pragma unroll
    for (int i = 0; i < 4; i++) {
        #pragma unroll
        for (int jp = 0; jp < 2; jp++) {
            int d0 = 2 * tx + 32 * jp;
            float2 v = unpack2(acc[i][jp]);
            float2 xb = *(const float2*)&Xb[m * NDS + d0];
            float2 hb = *(const float2*)&Hb[m * NDS + d0];
            v.x += xb.x + hb.x;
            v.y += xb.y + hb.y;
            *(float2*)&g_xp[((size_t)(bb * NS) + t0 + ty + 16 * i) * (NM * NDS) + m * NDS + d0] = v;
        }
    }
}

// ======================= Kernel 2: the sequential scan =====================
// R12 algorithm, refined decomposition: 768 threads (24 warps, 6/SMSP).
//   phase 1: 64 outputs x 12 segments of 16 elems  (8 fma2/thread)
//   z+W2   : warps 0..8 (unchanged), 12 partials
//   phase 4: 4 threads per output, 16-elem slice of all three dots
//            (24 fma2/thread), combine via 2 shfl_xor
// 3 block-wide syncs per step.
__global__ void __launch_bounds__(768, 1) scan_kernel(
    const float* __restrict__ W1, const float* __restrict__ b1,
    const float* __restrict__ W2, const float* __restrict__ b2,
    const float* __restrict__ HW, const float* __restrict__ CW)
{
    __shared__ __align__(16) float sh_h[2][NM * NDS];  // double-buffered state
    __shared__ __align__(16) float sh_part[12][NDS];   // z-partials [seg][o]
    __shared__ float sh_raw[12];

    const int u  = threadIdx.x;
    const int bb = blockIdx.x;
    const int lane = u & 31;
    const int wp   = u >> 5;          // warp id 0..23

    // phase-1 mapping: output o1 (0..63), segment seg (0..11) of 16 elems
    const int o1  = u & 63;
    const int seg = u >> 6;
    // phase-4 mapping: output o2 = m*64+d (0..191), quarter q (0..3)
    const int q    = u & 3;
    const int o2   = u >> 2;
    const int m4   = o2 >> 6;          // warp-uniform (u>>8)
    const int d4   = o2 & 63;
    const int s1 = (m4 == 0) ? 1 : 0;
    const int s2 = (m4 == 2) ? 1 : 2;

    // ---- weights into registers (packed f32 pairs) ----
    ull w1r[8];    // W1[o1][seg*16 .. +16)
    #pragma unroll
    for (int j = 0; j < 8; j++)
        w1r[j] = *(const ull*)(W1 + (size_t)o1 * (NM * NDS) + seg * 16 + 2 * j);

    ull whw[8];    // HW[m4][d4][q*16 .. +16)
    #pragma unroll
    for (int j = 0; j < 8; j++)
        whw[j] = *(const ull*)(HW + ((size_t)(m4 * NDS + d4)) * NDS + q * 16 + 2 * j);

    ull wc1[8];    // CW[m4][s1][d4][q*16 .. +16)
    #pragma unroll
    for (int j = 0; j < 8; j++)
        wc1[j] = *(const ull*)(CW + ((size_t)((m4 * NM + s1) * NDS + d4)) * NDS + q * 16 + 2 * j);

    ull wc2[8];    // CW[m4][s2][d4][q*16 .. +16)
    #pragma unroll
    for (int j = 0; j < 8; j++)
        wc2[j] = *(const ull*)(CW + ((size_t)((m4 * NM + s2) * NDS + d4)) * NDS + q * 16 + 2 * j);

    // gating constants: lane owns z[2*lane..2*lane+1] (warps 0..8 only)
    const float2 b1r = *(const float2*)(b1 + 2 * lane);
    ull w2l = 0;
    float b2p = 0.0f;
    if (wp < 9) {
        w2l = *(const ull*)(W2 + (size_t)wp * NDS + 2 * lane);
        b2p = b2[wp];
    }

    if (u < NM * NDS) sh_h[0][u] = 0.0f;
    __syncthreads();

    const float* xp_base = g_xp + (size_t)bb * NS * (NM * NDS) + o2;
    float* hn_base = g_hn + (size_t)bb * NS * (NM * NDS) + o2;

    for (int t = 0; t < NS; t++) {
        const int cur = t & 1, nxt = cur ^ 1;
        const float* hb = &sh_h[cur][0];

        // xp for this step (only q==0 consumes; issued early to hide L2)
        float xp_v = 0.0f;
        if (q == 0) xp_v = __ldg(xp_base + (size_t)t * (NM * NDS));

        // ---- phase 1: z-partials (seg of 16 elems, broadcast LDS) ----
        {
            const float* hseg = hb + seg * 16;
            ull a1 = 0, a2 = 0;
            #pragma unroll
            for (int j = 0; j < 4; j++) {
                ulonglong2 hv = *(const ulonglong2*)(hseg + 4 * j);
                fma2(a1, hv.x, w1r[2 * j]);
                fma2(a2, hv.y, w1r[2 * j + 1]);
            }
            sh_part[seg][o1] = sum2(a1) + sum2(a2);
        }
        __syncthreads();

        // ---- fused z + W2 stage: warps 0..8 rebuild their z pair ----
        if (wp < 9) {
            float2 zv = b1r;
            #pragma unroll
            for (int s = 0; s < 12; s++) {
                float2 pp = *(const float2*)&sh_part[s][2 * lane];
                zv.x += pp.x; zv.y += pp.y;
            }
            ull zp = pack2(tanh_fast(zv.x), tanh_fast(zv.y));
            ull qq = 0; fma2(qq, zp, w2l);
            float pr = sum2(qq);
            #pragma unroll
            for (int off = 16; off; off >>= 1)
                pr += __shfl_down_sync(0xffffffffu, pr, off);
            if (lane == 0) sh_raw[wp] = pr + b2p;
        }
        __syncthreads();

        // ---- phase 4: inline softmax + three 16-elem dot slices ----
        float r0 = sh_raw[m4 * 3 + 0];
        float r1 = sh_raw[m4 * 3 + 1];
        float r2 = sh_raw[m4 * 3 + 2];
        float e0 = __expf(r0), e1 = __expf(r1), e2 = __expf(r2);
        float inv = __frcp_rn(e0 + e1 + e2);
        float a1f = ((s1 == 0) ? e0 : e1) * inv;   // attn[m4][s1]
        float a2f = ((s2 == 1) ? e1 : e2) * inv;   // attn[m4][s2]

        const float* hm = hb + m4 * 64 + q * 16;
        const float* h1 = hb + s1 * 64 + q * 16;
        const float* h2 = hb + s2 * 64 + q * 16;
        ull ahw = 0, ac1 = 0, ac2 = 0;
        #pragma unroll
        for (int j = 0; j < 4; j++) {
            ulonglong2 hv = *(const ulonglong2*)(hm + 4 * j);
            fma2(ahw, hv.x, whw[2 * j]);
            fma2(ahw, hv.y, whw[2 * j + 1]);
        }
        #pragma unroll
        for (int j = 0; j < 4; j++) {
            ulonglong2 hv = *(const ulonglong2*)(h1 + 4 * j);
            fma2(ac1, hv.x, wc1[2 * j]);
            fma2(ac1, hv.y, wc1[2 * j + 1]);
        }
        #pragma unroll
        for (int j = 0; j < 4; j++) {
            ulonglong2 hv = *(const ulonglong2*)(h2 + 4 * j);
            fma2(ac2, hv.x, wc2[2 * j]);
            fma2(ac2, hv.y, wc2[2 * j + 1]);
        }

        float val = sum2(ahw) + a1f * sum2(ac1) + a2f * sum2(ac2);
        val += __shfl_xor_sync(0xffffffffu, val, 1);   // combine quarters
        val += __shfl_xor_sync(0xffffffffu, val, 2);
        if (q == 0) {
            float su = val + xp_v;
            float hn = su / (1.0f + __expf(-su));       // silu
            sh_h[nxt][o2] = hn;
            hn_base[(size_t)t * (NM * NDS)] = hn;
        }
        __syncthreads();
    }
}

// ======================= Kernel 3: y = OW@h_new + Ob; out = LN(y + x) ======
__global__ void __launch_bounds__(256) out_kernel(
    const float* __restrict__ xa, const float* __restrict__ xv, const float* __restrict__ xl,
    const float* __restrict__ OW, const float* __restrict__ Ob,
    const float* __restrict__ lng, const float* __restrict__ lnb,
    float* __restrict__ out)
{
    __shared__ __align__(16) float sh_ht[2][8][NDS];
    __shared__ float sh_red[2][8][2];

    const int tid = threadIdx.x;
    const int t0  = blockIdx.x * TS;
    const int bb  = blockIdx.y;
    const int m   = blockIdx.z;
    const float* xm = (m == 0) ? xa : ((m == 1) ? xv : xl);

    ull ow[32];
    #pragma unroll
    for (int j = 0; j < 32; j++)
        ow[j] = *(const ull*)(OW + ((size_t)m * ND + tid) * NDS + 2 * j);
    const float ob = Ob[m * ND + tid];
    const float gg = lng[m * ND + tid];
    const float be = lnb[m * ND + tid];

    const float* hn_base = g_hn + ((size_t)(bb * NS + t0)) * (NM * NDS) + m * NDS;
    const float* x_base  = xm + ((size_t)bb * NS + t0) * ND;
    float* o_base = out + ((size_t)m * NB + bb) * (size_t)NS * ND + (size_t)t0 * ND;

    const int ptt = tid >> 4;
    const int pq  = tid & 15;

    if (tid < 128) {
        int tc = min(0 * 8 + ptt, TS - 1);
        cp_async16(&sh_ht[0][ptt][pq * 4], hn_base + (size_t)tc * (NM * NDS) + pq * 4);
    }
    cp_commit();

    const int NG = TS / 8;
    for (int g = 0; g < NG; g++) {
        const int buf = g & 1;
        if (tid < 128) {
            int tc = min((g + 1) * 8 + ptt, TS - 1);
            cp_async16(&sh_ht[buf ^ 1][ptt][pq * 4], hn_base + (size_t)tc * (NM * NDS) + pq * 4);
        }
        cp_commit();
        cp_wait1();
        __syncthreads();

        #pragma unroll
        for (int k = 0; k < 8; k++) {
            const int t = g * 8 + k;
            float xval = __ldg(x_base + (size_t)t * ND + tid);

            ull acc = 0;
            #pragma unroll
            for (int j = 0; j < 32; j++)
                fma2(acc, *(const ull*)&sh_ht[buf][k][2 * j], ow[j]);
            float v = sum2(acc) + ob + xval;

            float s = v, ss = v * v;
            #pragma unroll
            for (int off = 16; off; off >>= 1) {
                s  += __shfl_xor_sync(0xffffffffu, s, off);
                ss += __shfl_xor_sync(0xffffffffu, ss, off);
            }
            const int w = tid >> 5, lw = tid & 31;
            const int rb = t & 1;
            if (lw == 0) { sh_red[rb][w][0] = s; sh_red[rb][w][1] = ss; }
            __syncthreads();
            float S = 0.0f, SS = 0.0f;
            #pragma unroll
            for (int w2 = 0; w2 < 8; w2++) { S += sh_red[rb][w2][0]; SS += sh_red[rb][w2][1]; }
            float mu  = S * (1.0f / 256.0f);
            float var = SS * (1.0f / 256.0f) - mu * mu;
            float r   = rsqrtf(var + 1e-5f);
            o_base[(size_t)t * ND + tid] = (v - mu) * r * gg + be;
        }
    }
}

// =============================== launch ====================================
extern "C" void kernel_launch(void* const* d_in, const int* in_sizes, int n_in,
                              void* d_out, int out_size) {
    const float* xa  = (const float*)d_in[0];
    const float* xv  = (const float*)d_in[1];
    const float* xl  = (const float*)d_in[2];
    const float* XW  = (const float*)d_in[3];
    const float* Xb  = (const float*)d_in[4];
    const float* HW  = (const float*)d_in[5];
    const float* Hb  = (const float*)d_in[6];
    const float* OW  = (const float*)d_in[7];
    const float* Ob  = (const float*)d_in[8];
    const float* CW  = (const float*)d_in[9];
    const float* W1  = (const float*)d_in[10];
    const float* b1  = (const float*)d_in[11];
    const float* W2  = (const float*)d_in[12];
    const float* b2  = (const float*)d_in[13];
    const float* lng = (const float*)d_in[14];
    const float* lnb = (const float*)d_in[15];
    float* out = (float*)d_out;

    dim3 gA(NS / 64, NB, NM);
    xproj_kernel<<<gA, 256>>>(xa, xv, xl, XW, Xb, Hb);

    scan_kernel<<<NB, 768>>>(W1, b1, W2, b2, HW, CW);

    dim3 gC(NS / TS, NB, NM);
    out_kernel<<<gC, 256>>>(xa, xv, xl, OW, Ob, lng, lnb, out);
}

// round 15
// speedup vs baseline: 1.3069x; 1.3069x over previous
#include <cuda_runtime.h>
#include <math.h>
#include <stdint.h>

#define NB 32
#define NS 1024
#define ND 256
#define NDS 64
#define NM 3
#define TS 128   // timesteps per out_kernel block

typedef unsigned long long ull;

// ---------------- scratch (device globals; no cudaMalloc allowed) ----------
__device__ float g_xp[(size_t)NB * NS * NM * NDS];   // [B][S][M*DS]  (XW@x + Xb + Hb)
__device__ float g_hn[(size_t)NB * NS * NM * NDS];   // [B][S][M*DS]  (h_new per step)

// ---------------- packed f32x2 helpers -------------------------------------
__device__ __forceinline__ void fma2(ull& acc, ull a, ull b) {
    asm("fma.rn.f32x2 %0, %1, %2, %0;" : "+l"(acc) : "l"(a), "l"(b));
}
__device__ __forceinline__ ull pack2(float x, float y) {
    ull r; asm("mov.b64 %0, {%1, %2};" : "=l"(r) : "f"(x), "f"(y)); return r;
}
__device__ __forceinline__ float2 unpack2(ull v) {
    float2 r; asm("mov.b64 {%0, %1}, %2;" : "=f"(r.x), "=f"(r.y) : "l"(v)); return r;
}
__device__ __forceinline__ float sum2(ull v) { float2 f = unpack2(v); return f.x + f.y; }

__device__ __forceinline__ float tanh_fast(float x) {
    float y; asm("tanh.approx.f32 %0, %1;" : "=f"(y) : "f"(x)); return y;
}

// ---------------- cluster / mbarrier helpers --------------------------------
__device__ __forceinline__ uint32_t smem_u32(const void* p) {
    return (uint32_t)__cvta_generic_to_shared(p);
}
__device__ __forceinline__ uint32_t my_cluster_rank() {
    uint32_t r; asm("mov.u32 %0, %%cluster_ctarank;" : "=r"(r)); return r;
}
__device__ __forceinline__ uint32_t mapa_u32(uint32_t addr, uint32_t rank) {
    uint32_t r;
    asm volatile("mapa.shared::cluster.u32 %0, %1, %2;" : "=r"(r) : "r"(addr), "r"(rank));
    return r;
}
__device__ __forceinline__ void st_cluster_f32(uint32_t addr, float v) {
    asm volatile("st.shared::cluster.f32 [%0], %1;" :: "r"(addr), "f"(v) : "memory");
}
__device__ __forceinline__ void mbar_init(uint32_t addr, uint32_t cnt) {
    asm volatile("mbarrier.init.shared.b64 [%0], %1;" :: "r"(addr), "r"(cnt) : "memory");
}
__device__ __forceinline__ void mbar_arrive_remote(uint32_t addr) {
    asm volatile("mbarrier.arrive.release.cluster.shared::cluster.b64 _, [%0];"
                 :: "r"(addr) : "memory");
}
__device__ __forceinline__ void mbar_wait(uint32_t addr, uint32_t phase) {
    asm volatile(
        "{\n\t.reg .pred P;\n\t"
        "WL_%=:\n\t"
        "mbarrier.try_wait.parity.acquire.cluster.shared::cta.b64 P, [%0], %1, 0x989680;\n\t"
        "@P bra.uni WD_%=;\n\t"
        "bra.uni WL_%=;\n\t"
        "WD_%=:\n\t}"
        :: "r"(addr), "r"(phase) : "memory");
}
__device__ __forceinline__ void cluster_sync_all() {
    asm volatile("barrier.cluster.arrive.aligned;" ::: "memory");
    asm volatile("barrier.cluster.wait.aligned;" ::: "memory");
}

// ---------------- cp.async helpers ------------------------------------------
__device__ __forceinline__ void cp_async16(void* smem_dst, const void* gsrc) {
    unsigned s = (unsigned)__cvta_generic_to_shared(smem_dst);
    asm volatile("cp.async.ca.shared.global [%0], [%1], 16;" :: "r"(s), "l"(gsrc));
}
__device__ __forceinline__ void cp_commit() { asm volatile("cp.async.commit_group;"); }
__device__ __forceinline__ void cp_wait1()  { asm volatile("cp.async.wait_group 1;"); }

// ======================= Kernel 1: xp = XW@x + Xb + Hb =====================
__global__ void __launch_bounds__(256) xproj_kernel(
    const float* __restrict__ xa, const float* __restrict__ xv, const float* __restrict__ xl,
    const float* __restrict__ XW, const float* __restrict__ Xb, const float* __restrict__ Hb)
{
    __shared__ __align__(16) float Xs[64][64];   // [t][k]
    __shared__ __align__(16) float Wt[64][64];   // [k][d] (XW transposed)

    const int m  = blockIdx.z;
    const int bb = blockIdx.y;
    const int t0 = blockIdx.x * 64;
    const float* xm = (m == 0) ? xa : ((m == 1) ? xv : xl);

    const int tid = threadIdx.x;
    const int tx = tid & 15, ty = tid >> 4;

    ull acc[4][2] = {};

    const int ldx_row = tid >> 2, ldx_q = tid & 3;
    const int ldw_d = tid & 63, ldw_g = tid >> 6;

    for (int kc = 0; kc < 4; kc++) {
        __syncthreads();
        #pragma unroll
        for (int g = 0; g < 4; g++) {
            int col = ldx_q * 16 + g * 4;
            float4 v = *(const float4*)&xm[((size_t)(bb * NS) + t0 + ldx_row) * ND + kc * 64 + col];
            *(float4*)&Xs[ldx_row][col] = v;
        }
        #pragma unroll
        for (int g = 0; g < 4; g++) {
            int kk = ldw_g * 16 + g * 4;
            float4 w = *(const float4*)&XW[((size_t)(m * NDS + ldw_d)) * ND + kc * 64 + kk];
            Wt[kk + 0][ldw_d] = w.x; Wt[kk + 1][ldw_d] = w.y;
            Wt[kk + 2][ldw_d] = w.z; Wt[kk + 3][ldw_d] = w.w;
        }
        __syncthreads();
        #pragma unroll 4
        for (int kq = 0; kq < 16; kq++) {
            float4 av[4];
            #pragma unroll
            for (int i = 0; i < 4; i++)
                av[i] = *(const float4*)&Xs[ty + 16 * i][4 * kq];
            #pragma unroll
            for (int q = 0; q < 4; q++) {
                const int kk = 4 * kq + q;
                ull bv0 = *(const ull*)&Wt[kk][2 * tx];
                ull bv1 = *(const ull*)&Wt[kk][2 * tx + 32];
                #pragma unroll
                for (int i = 0; i < 4; i++) {
                    float a = (q == 0) ? av[i].x : (q == 1) ? av[i].y
                            : (q == 2) ? av[i].z : av[i].w;
                    ull aa = pack2(a, a);
                    fma2(acc[i][0], aa, bv0);
                    fma2(acc[i][1], aa, bv1);
                }
            }
        }
    }
    #pragma unroll
    for (int i = 0; i < 4; i++) {
        #pragma unroll
        for (int jp = 0; jp < 2; jp++) {
            int d0 = 2 * tx + 32 * jp;
            float2 v = unpack2(acc[i][jp]);
            float2 xb = *(const float2*)&Xb[m * NDS + d0];
            float2 hb = *(const float2*)&Hb[m * NDS + d0];
            v.x += xb.x + hb.x;
            v.y += xb.y + hb.y;
            *(float2*)&g_xp[((size_t)(bb * NS) + t0 + ty + 16 * i) * (NM * NDS) + m * NDS + d0] = v;
        }
    }
}

// ======================= Kernel 2: cluster-split sequential scan ===========
// 96 blocks = 32 clusters of 3 CTAs (one per modality). 288 threads/CTA.
// Each CTA owns 64 outputs (its modality); full h replicated in every CTA's
// SMEM, kept coherent via DSMEM stores + mbarrier (count=128, double-buffered).
// Gating (z, W2, softmax) recomputed redundantly per CTA (small).
__global__ void __launch_bounds__(288, 1) __cluster_dims__(3, 1, 1)
scan_kernel(
    const float* __restrict__ W1, const float* __restrict__ b1,
    const float* __restrict__ W2, const float* __restrict__ b2,
    const float* __restrict__ HW, const float* __restrict__ CW)
{
    __shared__ __align__(16) float sh_h[2][NM * NDS];  // full state, both parities
    __shared__ __align__(16) float sh_part[4][NDS];    // z-partials [seg][o]
    __shared__ float sh_raw[12];
    __shared__ __align__(8) unsigned long long s_bar[2];

    const int u    = threadIdx.x;
    const int lane = u & 31;
    const int wp   = u >> 5;                 // 0..8
    const int bb   = blockIdx.x / 3;         // batch element
    const int r    = (int)my_cluster_rank(); // modality owned by this CTA
    const int s1 = (r == 0) ? 1 : 0;
    const int s2 = (r == 2) ? 1 : 2;

    // phase-1 mapping (u < 256): output o1, segment seg of 48 elems
    const int o1  = u & 63;
    const int seg = u >> 6;                  // 0..3
    // phase-4 mapping (u < 256): output d4 = u>>2 (0..63), quarter q = u&3
    const int q  = u & 3;
    const int d4 = u >> 2;
    const int og = r * 64 + d4;              // global output index

    // ---- weights in registers ----
    ull w1r[24];   // W1[o1][seg*48 .. +48)
    #pragma unroll
    for (int j = 0; j < 24; j++)
        w1r[j] = *(const ull*)(W1 + (size_t)o1 * (NM * NDS) + seg * 48 + 2 * j);

    ull whw[8];    // HW[r][d4][q*16 .. +16)
    #pragma unroll
    for (int j = 0; j < 8; j++)
        whw[j] = *(const ull*)(HW + ((size_t)(r * NDS + d4)) * NDS + q * 16 + 2 * j);

    ull wc1[8];    // CW[r][s1][d4][q*16 .. +16)
    #pragma unroll
    for (int j = 0; j < 8; j++)
        wc1[j] = *(const ull*)(CW + ((size_t)((r * NM + s1) * NDS + d4)) * NDS + q * 16 + 2 * j);

    ull wc2[8];    // CW[r][s2][d4][q*16 .. +16)
    #pragma unroll
    for (int j = 0; j < 8; j++)
        wc2[j] = *(const ull*)(CW + ((size_t)((r * NM + s2) * NDS + d4)) * NDS + q * 16 + 2 * j);

    // gating constants (all 9 warps): lane owns z[2*lane..+1], warp wp owns W2 row wp
    const float2 b1r = *(const float2*)(b1 + 2 * lane);
    const ull   w2l  = *(const ull*)(W2 + (size_t)wp * NDS + 2 * lane);
    const float b2p  = b2[wp];

    // ---- DSMEM addresses ----
    const uint32_t rA = (uint32_t)((r + 1) % 3);
    const uint32_t rB = (uint32_t)((r + 2) % 3);
    const uint32_t hbase  = smem_u32(&sh_h[0][0]);
    const uint32_t pA_h   = mapa_u32(hbase, rA);
    const uint32_t pB_h   = mapa_u32(hbase, rB);
    const uint32_t bar0   = smem_u32(&s_bar[0]);
    const uint32_t bar1   = smem_u32(&s_bar[1]);
    const uint32_t pA_bar[2] = { mapa_u32(bar0, rA), mapa_u32(bar1, rA) };
    const uint32_t pB_bar[2] = { mapa_u32(bar0, rB), mapa_u32(bar1, rB) };
    const uint32_t my_bar[2] = { bar0, bar1 };

    // ---- init ----
    if (u < NM * NDS) sh_h[0][u] = 0.0f;
    if (u == 0) { mbar_init(bar0, 128); mbar_init(bar1, 128); }
    __syncthreads();
    cluster_sync_all();   // all CTAs' barriers initialized, h0 zeroed

    const float* xp_base = g_xp + (size_t)bb * NS * (NM * NDS) + og;
    float* hn_base = g_hn + (size_t)bb * NS * (NM * NDS) + og;

    for (int t = 0; t < NS; t++) {
        const int cur = t & 1, nxt = cur ^ 1;

        // wait for peers' h contributions for this step
        if (t > 0) {
            uint32_t ph = (cur == 1) ? (uint32_t)((t >> 1) & 1)
                                     : (uint32_t)(((t >> 1) + 1) & 1);
            mbar_wait(my_bar[cur], ph);
        }
        const float* hb = &sh_h[cur][0];

        // xp for this step (only q==0 consumes; issued early)
        float xp_v = 0.0f;
        if (u < 256 && q == 0) xp_v = __ldg(xp_base + (size_t)t * (NM * NDS));

        // ---- phase 1: z-partials (u < 256) ----
        if (u < 256) {
            const float* hseg = hb + seg * 48;
            ull a0 = 0, a1 = 0, a2 = 0, a3 = 0;
            #pragma unroll
            for (int j = 0; j < 12; j++) {
                ulonglong2 hv = *(const ulonglong2*)(hseg + 4 * j);
                if (j & 1) { fma2(a2, hv.x, w1r[2 * j]); fma2(a3, hv.y, w1r[2 * j + 1]); }
                else       { fma2(a0, hv.x, w1r[2 * j]); fma2(a1, hv.y, w1r[2 * j + 1]); }
            }
            sh_part[seg][o1] = sum2(a0) + sum2(a1) + sum2(a2) + sum2(a3);
        }
        __syncthreads();

        // ---- fused z + W2 stage: all 9 warps, one W2 row each ----
        {
            float2 zv = b1r;
            #pragma unroll
            for (int s = 0; s < 4; s++) {
                float2 pp = *(const float2*)&sh_part[s][2 * lane];
                zv.x += pp.x; zv.y += pp.y;
            }
            ull zp = pack2(tanh_fast(zv.x), tanh_fast(zv.y));
            ull qq = 0; fma2(qq, zp, w2l);
            float pr = sum2(qq);
            #pragma unroll
            for (int off = 16; off; off >>= 1)
                pr += __shfl_down_sync(0xffffffffu, pr, off);
            if (lane == 0) sh_raw[wp] = pr + b2p;
        }
        __syncthreads();

        // ---- phase 4: softmax + dots, 4 threads per output (u < 256) ----
        if (u < 256) {
            float r0 = sh_raw[r * 3 + 0];
            float r1 = sh_raw[r * 3 + 1];
            float r2 = sh_raw[r * 3 + 2];
            float e0 = __expf(r0), e1 = __expf(r1), e2 = __expf(r2);
            float inv = __frcp_rn(e0 + e1 + e2);
            float a1f = ((s1 == 0) ? e0 : e1) * inv;   // attn[r][s1]
            float a2f = ((s2 == 1) ? e1 : e2) * inv;   // attn[r][s2]

            const float* hm = hb + r  * 64 + q * 16;
            const float* h1 = hb + s1 * 64 + q * 16;
            const float* h2 = hb + s2 * 64 + q * 16;
            ull ahw = 0, ac1 = 0, ac2 = 0;
            #pragma unroll
            for (int j = 0; j < 4; j++) {
                ulonglong2 hv = *(const ulonglong2*)(hm + 4 * j);
                fma2(ahw, hv.x, whw[2 * j]);
                fma2(ahw, hv.y, whw[2 * j + 1]);
            }
            #pragma unroll
            for (int j = 0; j < 4; j++) {
                ulonglong2 hv = *(const ulonglong2*)(h1 + 4 * j);
                fma2(ac1, hv.x, wc1[2 * j]);
                fma2(ac1, hv.y, wc1[2 * j + 1]);
            }
            #pragma unroll
            for (int j = 0; j < 4; j++) {
                ulonglong2 hv = *(const ulonglong2*)(h2 + 4 * j);
                fma2(ac2, hv.x, wc2[2 * j]);
                fma2(ac2, hv.y, wc2[2 * j + 1]);
            }

            float val = sum2(ahw) + a1f * sum2(ac1) + a2f * sum2(ac2);
            val += __shfl_xor_sync(0xffffffffu, val, 1);
            val += __shfl_xor_sync(0xffffffffu, val, 2);
            if (q == 0) {
                float su = val + xp_v;
                float hn = su / (1.0f + __expf(-su));   // silu
                sh_h[nxt][og] = hn;                      // local copy
                uint32_t off = (uint32_t)((nxt * (NM * NDS) + og) * 4);
                st_cluster_f32(pA_h + off, hn);          // peer copies
                st_cluster_f32(pB_h + off, hn);
                hn_base[(size_t)t * (NM * NDS)] = hn;
                mbar_arrive_remote(pA_bar[nxt]);         // release our stores
                mbar_arrive_remote(pB_bar[nxt]);
            }
        }
        __syncthreads();
    }
    cluster_sync_all();   // no CTA exits while peers' DSMEM ops may target it
}

// ======================= Kernel 3: y = OW@h_new + Ob; out = LN(y + x) ======
__global__ void __launch_bounds__(256) out_kernel(
    const float* __restrict__ xa, const float* __restrict__ xv, const float* __restrict__ xl,
    const float* __restrict__ OW, const float* __restrict__ Ob,
    const float* __restrict__ lng, const float* __restrict__ lnb,
    float* __restrict__ out)
{
    __shared__ __align__(16) float sh_ht[2][8][NDS];
    __shared__ float sh_red[2][8][2];

    const int tid = threadIdx.x;
    const int t0  = blockIdx.x * TS;
    const int bb  = blockIdx.y;
    const int m   = blockIdx.z;
    const float* xm = (m == 0) ? xa : ((m == 1) ? xv : xl);

    ull ow[32];
    #pragma unroll
    for (int j = 0; j < 32; j++)
        ow[j] = *(const ull*)(OW + ((size_t)m * ND + tid) * NDS + 2 * j);
    const float ob = Ob[m * ND + tid];
    const float gg = lng[m * ND + tid];
    const float be = lnb[m * ND + tid];

    const float* hn_base = g_hn + ((size_t)(bb * NS + t0)) * (NM * NDS) + m * NDS;
    const float* x_base  = xm + ((size_t)bb * NS + t0) * ND;
    float* o_base = out + ((size_t)m * NB + bb) * (size_t)NS * ND + (size_t)t0 * ND;

    const int ptt = tid >> 4;
    const int pq  = tid & 15;

    if (tid < 128) {
        int tc = min(0 * 8 + ptt, TS - 1);
        cp_async16(&sh_ht[0][ptt][pq * 4], hn_base + (size_t)tc * (NM * NDS) + pq * 4);
    }
    cp_commit();

    const int NG = TS / 8;
    for (int g = 0; g < NG; g++) {
        const int buf = g & 1;
        if (tid < 128) {
            int tc = min((g + 1) * 8 + ptt, TS - 1);
            cp_async16(&sh_ht[buf ^ 1][ptt][pq * 4], hn_base + (size_t)tc * (NM * NDS) + pq * 4);
        }
        cp_commit();
        cp_wait1();
        __syncthreads();

        #pragma unroll
        for (int k = 0; k < 8; k++) {
            const int t = g * 8 + k;
            float xval = __ldg(x_base + (size_t)t * ND + tid);

            ull acc = 0;
            #pragma unroll
            for (int j = 0; j < 32; j++)
                fma2(acc, *(const ull*)&sh_ht[buf][k][2 * j], ow[j]);
            float v = sum2(acc) + ob + xval;

            float s = v, ss = v * v;
            #pragma unroll
            for (int off = 16; off; off >>= 1) {
                s  += __shfl_xor_sync(0xffffffffu, s, off);
                ss += __shfl_xor_sync(0xffffffffu, ss, off);
            }
            const int w = tid >> 5, lw = tid & 31;
            const int rb = t & 1;
            if (lw == 0) { sh_red[rb][w][0] = s; sh_red[rb][w][1] = ss; }
            __syncthreads();
            float S = 0.0f, SS = 0.0f;
            #pragma unroll
            for (int w2 = 0; w2 < 8; w2++) { S += sh_red[rb][w2][0]; SS += sh_red[rb][w2][1]; }
            float mu  = S * (1.0f / 256.0f);
            float var = SS * (1.0f / 256.0f) - mu * mu;
            float r   = rsqrtf(var + 1e-5f);
            o_base[(size_t)t * ND + tid] = (v - mu) * r * gg + be;
        }
    }
}

// =============================== launch ====================================
extern "C" void kernel_launch(void* const* d_in, const int* in_sizes, int n_in,
                              void* d_out, int out_size) {
    const float* xa  = (const float*)d_in[0];
    const float* xv  = (const float*)d_in[1];
    const float* xl  = (const float*)d_in[2];
    const float* XW  = (const float*)d_in[3];
    const float* Xb  = (const float*)d_in[4];
    const float* HW  = (const float*)d_in[5];
    const float* Hb  = (const float*)d_in[6];
    const float* OW  = (const float*)d_in[7];
    const float* Ob  = (const float*)d_in[8];
    const float* CW  = (const float*)d_in[9];
    const float* W1  = (const float*)d_in[10];
    const float* b1  = (const float*)d_in[11];
    const float* W2  = (const float*)d_in[12];
    const float* b2  = (const float*)d_in[13];
    const float* lng = (const float*)d_in[14];
    const float* lnb = (const float*)d_in[15];
    float* out = (float*)d_out;

    dim3 gA(NS / 64, NB, NM);
    xproj_kernel<<<gA, 256>>>(xa, xv, xl, XW, Xb, Hb);

    // 96 CTAs = 32 clusters of 3 (cluster dims are a compile-time attribute)
    scan_kernel<<<NB * NM, 288>>>(W1, b1, W2, b2, HW, CW);

    dim3 gC(NS / TS, NB, NM);
    out_kernel<<<gC, 256>>>(xa, xv, xl, OW, Ob, lng, lnb, out);
}

// round 16
// speedup vs baseline: 2.0141x; 1.5411x over previous
#include <cuda_runtime.h>
#include <math.h>

#define NB 32
#define NS 1024
#define ND 256
#define NDS 64
#define NM 3
#define TS 128   // timesteps per out_kernel block

typedef unsigned long long ull;

// ---------------- scratch (device globals; no cudaMalloc allowed) ----------
__device__ float g_xp[(size_t)NB * NS * NM * NDS];   // [B][S][M*DS]  (XW@x + Xb + Hb)
__device__ float g_hn[(size_t)NB * NS * NM * NDS];   // [B][S][M*DS]  (h_new per step)

// ---------------- packed f32x2 helpers -------------------------------------
__device__ __forceinline__ void fma2(ull& acc, ull a, ull b) {
    asm("fma.rn.f32x2 %0, %1, %2, %0;" : "+l"(acc) : "l"(a), "l"(b));
}
__device__ __forceinline__ ull pack2(float x, float y) {
    ull r; asm("mov.b64 %0, {%1, %2};" : "=l"(r) : "f"(x), "f"(y)); return r;
}
__device__ __forceinline__ float2 unpack2(ull v) {
    float2 r; asm("mov.b64 {%0, %1}, %2;" : "=f"(r.x), "=f"(r.y) : "l"(v)); return r;
}
__device__ __forceinline__ float sum2(ull v) { float2 f = unpack2(v); return f.x + f.y; }

__device__ __forceinline__ float tanh_fast(float x) {
    float y; asm("tanh.approx.f32 %0, %1;" : "=f"(y) : "f"(x)); return y;
}

// ---------------- cp.async helpers ------------------------------------------
__device__ __forceinline__ void cp_async16(void* smem_dst, const void* gsrc) {
    unsigned s = (unsigned)__cvta_generic_to_shared(smem_dst);
    asm volatile("cp.async.ca.shared.global [%0], [%1], 16;" :: "r"(s), "l"(gsrc));
}
__device__ __forceinline__ void cp_commit() { asm volatile("cp.async.commit_group;"); }
__device__ __forceinline__ void cp_wait1()  { asm volatile("cp.async.wait_group 1;"); }

// ======================= Kernel 1: xp = XW@x + Xb + Hb =====================
// vs baseline: B operand read as ONE LDS.128 (d = 4*tx..+3), float4 epilogue.
__global__ void __launch_bounds__(256) xproj_kernel(
    const float* __restrict__ xa, const float* __restrict__ xv, const float* __restrict__ xl,
    const float* __restrict__ XW, const float* __restrict__ Xb, const float* __restrict__ Hb)
{
    __shared__ __align__(16) float Xs[64][64];   // [t][k]
    __shared__ __align__(16) float Wt[64][64];   // [k][d] (XW transposed)

    const int m  = blockIdx.z;
    const int bb = blockIdx.y;
    const int t0 = blockIdx.x * 64;
    const float* xm = (m == 0) ? xa : ((m == 1) ? xv : xl);

    const int tid = threadIdx.x;
    const int tx = tid & 15, ty = tid >> 4;

    ull acc[4][2] = {};

    const int ldx_row = tid >> 2, ldx_q = tid & 3;
    const int ldw_d = tid & 63, ldw_g = tid >> 6;

    for (int kc = 0; kc < 4; kc++) {
        __syncthreads();
        #pragma unroll
        for (int g = 0; g < 4; g++) {
            int col = ldx_q * 16 + g * 4;
            float4 v = *(const float4*)&xm[((size_t)(bb * NS) + t0 + ldx_row) * ND + kc * 64 + col];
            *(float4*)&Xs[ldx_row][col] = v;
        }
        #pragma unroll
        for (int g = 0; g < 4; g++) {
            int kk = ldw_g * 16 + g * 4;
            float4 w = *(const float4*)&XW[((size_t)(m * NDS + ldw_d)) * ND + kc * 64 + kk];
            Wt[kk + 0][ldw_d] = w.x; Wt[kk + 1][ldw_d] = w.y;
            Wt[kk + 2][ldw_d] = w.z; Wt[kk + 3][ldw_d] = w.w;
        }
        __syncthreads();
        #pragma unroll 4
        for (int kq = 0; kq < 16; kq++) {
            float4 av[4];
            #pragma unroll
            for (int i = 0; i < 4; i++)
                av[i] = *(const float4*)&Xs[ty + 16 * i][4 * kq];
            #pragma unroll
            for (int q = 0; q < 4; q++) {
                const int kk = 4 * kq + q;
                ulonglong2 bv = *(const ulonglong2*)&Wt[kk][4 * tx];
                #pragma unroll
                for (int i = 0; i < 4; i++) {
                    float a = (q == 0) ? av[i].x : (q == 1) ? av[i].y
                            : (q == 2) ? av[i].z : av[i].w;
                    ull aa = pack2(a, a);
                    fma2(acc[i][0], aa, bv.x);
                    fma2(acc[i][1], aa, bv.y);
                }
            }
        }
    }
    {
        const int d0 = 4 * tx;
        float4 xb = *(const float4*)&Xb[m * NDS + d0];
        float4 hb = *(const float4*)&Hb[m * NDS + d0];
        #pragma unroll
        for (int i = 0; i < 4; i++) {
            float2 lo = unpack2(acc[i][0]);
            float2 hi = unpack2(acc[i][1]);
            float4 v;
            v.x = lo.x + xb.x + hb.x;
            v.y = lo.y + xb.y + hb.y;
            v.z = hi.x + xb.z + hb.z;
            v.w = hi.y + xb.w + hb.w;
            *(float4*)&g_xp[((size_t)(bb * NS) + t0 + ty + 16 * i) * (NM * NDS) + m * NDS + d0] = v;
        }
    }
}

// ======================= Kernel 2: the sequential scan =====================
// R12 skeleton (384 threads, weights in regs) with the gating tail inlined:
//   phase 1: z-partials -> sh_part                        [sync]
//   phase 2: EVERY warp rebuilds z, computes its own 3 W2 rows (3 parallel
//            shfl trees), softmax inline — overlapped with its HW/CW dots;
//            combine, silu, store                          [sync]
// TWO __syncthreads per step (was three). W1 stays in registers (R11 lesson).
__global__ void __launch_bounds__(384, 1) scan_kernel(
    const float* __restrict__ W1, const float* __restrict__ b1,
    const float* __restrict__ W2, const float* __restrict__ b2,
    const float* __restrict__ HW, const float* __restrict__ CW)
{
    __shared__ __align__(16) float sh_h[2][NM][NDS];  // double-buffered state
    __shared__ float sh_part[6][NDS];

    const int u  = threadIdx.x;
    const int bb = blockIdx.x;
    const int lane = u & 31;

    // phase-1 mapping: output o1 (0..63), hc segment seg (0..5) of 32 elems
    const int o1  = u & 63;
    const int seg = u >> 6;
    // phase-2 mapping: output o2 = m*64+d (0..191), dot-half (0/1)
    const int half = u & 1;
    const int o2   = u >> 1;
    const int m4   = o2 >> 6;          // warp-uniform
    const int d4   = o2 & 63;
    const int s1 = (m4 == 0) ? 1 : 0;
    const int s2 = (m4 == 2) ? 1 : 2;
    const int src = half ? s2 : s1;

    // ---- weights into registers (packed f32 pairs) — R12 layout ----
    ull w1r[16];
    #pragma unroll
    for (int j = 0; j < 16; j++)
        w1r[j] = *(const ull*)(W1 + o1 * (NM * NDS) + seg * 32 + 2 * j);

    ull whw[16];   // HW[m4][d4][half*32 .. half*32+32)
    #pragma unroll
    for (int j = 0; j < 16; j++)
        whw[j] = *(const ull*)(HW + ((size_t)(m4 * NDS + d4)) * NDS + half * 32 + 2 * j);

    ull wcw[32];   // CW[m4][src][d4][0..64)
    #pragma unroll
    for (int j = 0; j < 32; j++)
        wcw[j] = *(const ull*)(CW + ((size_t)((m4 * NM + src) * NDS + d4)) * NDS + 2 * j);

    // gating constants: lane owns z[2*lane..+1]; warp needs W2 rows 3*m4..+2
    const float2 b1r = *(const float2*)(b1 + 2 * lane);
    ull w2r[3];
    #pragma unroll
    for (int j = 0; j < 3; j++)
        w2r[j] = *(const ull*)(W2 + (size_t)(3 * m4 + j) * NDS + 2 * lane);
    const float b2r0 = b2[3 * m4 + 0];
    const float b2r1 = b2[3 * m4 + 1];
    const float b2r2 = b2[3 * m4 + 2];

    if (u < NM * NDS) (&sh_h[0][0][0])[u] = 0.0f;
    __syncthreads();

    const float* xp_base = g_xp + (size_t)bb * NS * (NM * NDS);
    float xp_c = __ldg(xp_base + o2);      // t = 0

    for (int t = 0; t < NS; t++) {
        const int cur = t & 1, nxt = cur ^ 1;
        const int tn = (t + 1 < NS) ? (t + 1) : t;
        float xp_n = __ldg(xp_base + (size_t)tn * (NM * NDS) + o2);  // prefetch

        // ---- phase 1: z-partials: W1 row o1, segment seg of hc ----
        const float* hseg = &sh_h[cur][0][0] + seg * 32;
        ull a1 = 0, a2 = 0;
        #pragma unroll
        for (int j = 0; j < 8; j++) {
            ulonglong2 hv = *(const ulonglong2*)(hseg + 4 * j);
            fma2(a1, hv.x, w1r[2 * j]);
            fma2(a2, hv.y, w1r[2 * j + 1]);
        }
        sh_part[seg][o1] = sum2(a1) + sum2(a2);
        __syncthreads();

        // ---- inline gating: rebuild z, 3 W2 rows, 3 parallel shfl trees ----
        float2 zv = b1r;
        #pragma unroll
        for (int s = 0; s < 6; s++) {
            float2 pp = *(const float2*)&sh_part[s][2 * lane];
            zv.x += pp.x; zv.y += pp.y;
        }
        ull zp = pack2(tanh_fast(zv.x), tanh_fast(zv.y));
        ull q0 = 0, q1 = 0, q2 = 0;
        fma2(q0, zp, w2r[0]); fma2(q1, zp, w2r[1]); fma2(q2, zp, w2r[2]);
        float r0 = sum2(q0), r1 = sum2(q1), r2 = sum2(q2);
        #pragma unroll
        for (int off = 16; off; off >>= 1) {
            r0 += __shfl_xor_sync(0xffffffffu, r0, off);
            r1 += __shfl_xor_sync(0xffffffffu, r1, off);
            r2 += __shfl_xor_sync(0xffffffffu, r2, off);
        }

        // ---- dots (independent of gating until the final combine) ----
        const float* hm = &sh_h[cur][m4][0] + half * 32;
        const float* hs = &sh_h[cur][src][0];
        ull ah0 = 0, ah1 = 0, c0 = 0, c1 = 0, c2 = 0, c3 = 0;
        #pragma unroll
        for (int j = 0; j < 8; j++) {
            ulonglong2 hv = *(const ulonglong2*)(hm + 4 * j);
            fma2(ah0, hv.x, whw[2 * j]);
            fma2(ah1, hv.y, whw[2 * j + 1]);
        }
        #pragma unroll
        for (int j = 0; j < 16; j++) {
            ulonglong2 hv = *(const ulonglong2*)(hs + 4 * j);
            if (j & 1) { fma2(c2, hv.x, wcw[2 * j]); fma2(c3, hv.y, wcw[2 * j + 1]); }
            else       { fma2(c0, hv.x, wcw[2 * j]); fma2(c1, hv.y, wcw[2 * j + 1]); }
        }

        // ---- softmax (row m4; mask after softmax per reference) ----
        float e0 = __expf(r0 + b2r0), e1 = __expf(r1 + b2r1), e2 = __expf(r2 + b2r2);
        float inv = __frcp_rn(e0 + e1 + e2);
        float esrc = (src == 0) ? e0 : ((src == 1) ? e1 : e2);
        float a = esrc * inv;          // src != m4 always

        float val = sum2(ah0) + sum2(ah1)
                  + a * (sum2(c0) + sum2(c1) + sum2(c2) + sum2(c3));
        val += __shfl_xor_sync(0xffffffffu, val, 1);   // combine halves
        if (half == 0) {
            float su = val + xp_c;
            float hn = su / (1.0f + __expf(-su));       // silu
            sh_h[nxt][m4][d4] = hn;
            g_hn[((size_t)(bb * NS + t)) * (NM * NDS) + o2] = hn;
        }
        xp_c = xp_n;
        __syncthreads();
    }
}

// ======================= Kernel 3: y = OW@h_new + Ob; out = LN(y + x) ======
// (unchanged from the 1581us baseline)
__global__ void __launch_bounds__(256) out_kernel(
    const float* __restrict__ xa, const float* __restrict__ xv, const float* __restrict__ xl,
    const float* __restrict__ OW, const float* __restrict__ Ob,
    const float* __restrict__ lng, const float* __restrict__ lnb,
    float* __restrict__ out)
{
    __shared__ __align__(16) float sh_ht[2][8][NDS];
    __shared__ float sh_red[2][8][2];

    const int tid = threadIdx.x;
    const int t0  = blockIdx.x * TS;
    const int bb  = blockIdx.y;
    const int m   = blockIdx.z;
    const float* xm = (m == 0) ? xa : ((m == 1) ? xv : xl);

    ull ow[32];
    #pragma unroll
    for (int j = 0; j < 32; j++)
        ow[j] = *(const ull*)(OW + ((size_t)m * ND + tid) * NDS + 2 * j);
    const float ob = Ob[m * ND + tid];
    const float gg = lng[m * ND + tid];
    const float be = lnb[m * ND + tid];

    const float* hn_base = g_hn + ((size_t)(bb * NS + t0)) * (NM * NDS) + m * NDS;
    const float* x_base  = xm + ((size_t)bb * NS + t0) * ND;
    float* o_base = out + ((size_t)m * NB + bb) * (size_t)NS * ND + (size_t)t0 * ND;

    const int ptt = tid >> 4;
    const int pq  = tid & 15;

    if (tid < 128) {
        int tc = min(0 * 8 + ptt, TS - 1);
        cp_async16(&sh_ht[0][ptt][pq * 4], hn_base + (size_t)tc * (NM * NDS) + pq * 4);
    }
    cp_commit();

    const int NG = TS / 8;
    for (int g = 0; g < NG; g++) {
        const int buf = g & 1;
        if (tid < 128) {
            int tc = min((g + 1) * 8 + ptt, TS - 1);
            cp_async16(&sh_ht[buf ^ 1][ptt][pq * 4], hn_base + (size_t)tc * (NM * NDS) + pq * 4);
        }
        cp_commit();
        cp_wait1();
        __syncthreads();

        #pragma unroll
        for (int k = 0; k < 8; k++) {
            const int t = g * 8 + k;
            float xval = __ldg(x_base + (size_t)t * ND + tid);

            ull acc = 0;
            #pragma unroll
            for (int j = 0; j < 32; j++)
                fma2(acc, *(const ull*)&sh_ht[buf][k][2 * j], ow[j]);
            float v = sum2(acc) + ob + xval;

            float s = v, ss = v * v;
            #pragma unroll
            for (int off = 16; off; off >>= 1) {
                s  += __shfl_xor_sync(0xffffffffu, s, off);
                ss += __shfl_xor_sync(0xffffffffu, ss, off);
            }
            const int w = tid >> 5, lw = tid & 31;
            const int rb = t & 1;
            if (lw == 0) { sh_red[rb][w][0] = s; sh_red[rb][w][1] = ss; }
            __syncthreads();
            float S = 0.0f, SS = 0.0f;
            #pragma unroll
            for (int w2 = 0; w2 < 8; w2++) { S += sh_red[rb][w2][0]; SS += sh_red[rb][w2][1]; }
            float mu  = S * (1.0f / 256.0f);
            float var = SS * (1.0f / 256.0f) - mu * mu;
            float r   = rsqrtf(var + 1e-5f);
            o_base[(size_t)t * ND + tid] = (v - mu) * r * gg + be;
        }
    }
}

// =============================== launch ====================================
extern "C" void kernel_launch(void* const* d_in, const int* in_sizes, int n_in,
                              void* d_out, int out_size) {
    const float* xa  = (const float*)d_in[0];
    const float* xv  = (const float*)d_in[1];
    const float* xl  = (const float*)d_in[2];
    const float* XW  = (const float*)d_in[3];
    const float* Xb  = (const float*)d_in[4];
    const float* HW  = (const float*)d_in[5];
    const float* Hb  = (const float*)d_in[6];
    const float* OW  = (const float*)d_in[7];
    const float* Ob  = (const float*)d_in[8];
    const float* CW  = (const float*)d_in[9];
    const float* W1  = (const float*)d_in[10];
    const float* b1  = (const float*)d_in[11];
    const float* W2  = (const float*)d_in[12];
    const float* b2  = (const float*)d_in[13];
    const float* lng = (const float*)d_in[14];
    const float* lnb = (const float*)d_in[15];
    float* out = (float*)d_out;

    dim3 gA(NS / 64, NB, NM);
    xproj_kernel<<<gA, 256>>>(xa, xv, xl, XW, Xb, Hb);

    scan_kernel<<<NB, 384>>>(W1, b1, W2, b2, HW, CW);

    dim3 gC(NS / TS, NB, NM);
    out_kernel<<<gC, 256>>>(xa, xv, xl, OW, Ob, lng, lnb, out);
}

// round 17
// speedup vs baseline: 2.1133x; 1.0493x over previous
#include <cuda_runtime.h>
#include <math.h>

#define NB 32
#define NS 1024
#define ND 256
#define NDS 64
#define NM 3
#define TS 128   // timesteps per out_kernel block

typedef unsigned long long ull;

// ---------------- scratch (device globals; no cudaMalloc allowed) ----------
__device__ float g_xp[(size_t)NB * NS * NM * NDS];   // [B][S][M*DS]  (XW@x + Xb + Hb)
__device__ float g_hn[(size_t)NB * NS * NM * NDS];   // [B][S][M*DS]  (h_new per step)

// ---------------- packed f32x2 helpers -------------------------------------
__device__ __forceinline__ void fma2(ull& acc, ull a, ull b) {
    asm("fma.rn.f32x2 %0, %1, %2, %0;" : "+l"(acc) : "l"(a), "l"(b));
}
__device__ __forceinline__ ull pack2(float x, float y) {
    ull r; asm("mov.b64 %0, {%1, %2};" : "=l"(r) : "f"(x), "f"(y)); return r;
}
__device__ __forceinline__ float2 unpack2(ull v) {
    float2 r; asm("mov.b64 {%0, %1}, %2;" : "=f"(r.x), "=f"(r.y) : "l"(v)); return r;
}
__device__ __forceinline__ float sum2(ull v) { float2 f = unpack2(v); return f.x + f.y; }

__device__ __forceinline__ float tanh_fast(float x) {
    float y; asm("tanh.approx.f32 %0, %1;" : "=f"(y) : "f"(x)); return y;
}
__device__ __forceinline__ float rcp_fast(float x) {
    float y; asm("rcp.approx.f32 %0, %1;" : "=f"(y) : "f"(x)); return y;
}

// ---------------- cp.async helpers ------------------------------------------
__device__ __forceinline__ void cp_async16(void* smem_dst, const void* gsrc) {
    unsigned s = (unsigned)__cvta_generic_to_shared(smem_dst);
    asm volatile("cp.async.ca.shared.global [%0], [%1], 16;" :: "r"(s), "l"(gsrc));
}
__device__ __forceinline__ void cp_commit() { asm volatile("cp.async.commit_group;"); }
__device__ __forceinline__ void cp_wait1()  { asm volatile("cp.async.wait_group 1;"); }

// ======================= Kernel 1: xp = XW@x + Xb + Hb =====================
// (R16 variant: single LDS.128 B-operand, float4 epilogue — 124.4us)
__global__ void __launch_bounds__(256) xproj_kernel(
    const float* __restrict__ xa, const float* __restrict__ xv, const float* __restrict__ xl,
    const float* __restrict__ XW, const float* __restrict__ Xb, const float* __restrict__ Hb)
{
    __shared__ __align__(16) float Xs[64][64];   // [t][k]
    __shared__ __align__(16) float Wt[64][64];   // [k][d] (XW transposed)

    const int m  = blockIdx.z;
    const int bb = blockIdx.y;
    const int t0 = blockIdx.x * 64;
    const float* xm = (m == 0) ? xa : ((m == 1) ? xv : xl);

    const int tid = threadIdx.x;
    const int tx = tid & 15, ty = tid >> 4;

    ull acc[4][2] = {};

    const int ldx_row = tid >> 2, ldx_q = tid & 3;
    const int ldw_d = tid & 63, ldw_g = tid >> 6;

    for (int kc = 0; kc < 4; kc++) {
        __syncthreads();
        #pragma unroll
        for (int g = 0; g < 4; g++) {
            int col = ldx_q * 16 + g * 4;
            float4 v = *(const float4*)&xm[((size_t)(bb * NS) + t0 + ldx_row) * ND + kc * 64 + col];
            *(float4*)&Xs[ldx_row][col] = v;
        }
        #pragma unroll
        for (int g = 0; g < 4; g++) {
            int kk = ldw_g * 16 + g * 4;
            float4 w = *(const float4*)&XW[((size_t)(m * NDS + ldw_d)) * ND + kc * 64 + kk];
            Wt[kk + 0][ldw_d] = w.x; Wt[kk + 1][ldw_d] = w.y;
            Wt[kk + 2][ldw_d] = w.z; Wt[kk + 3][ldw_d] = w.w;
        }
        __syncthreads();
        #pragma unroll 4
        for (int kq = 0; kq < 16; kq++) {
            float4 av[4];
            #pragma unroll
            for (int i = 0; i < 4; i++)
                av[i] = *(const float4*)&Xs[ty + 16 * i][4 * kq];
            #pragma unroll
            for (int q = 0; q < 4; q++) {
                const int kk = 4 * kq + q;
                ulonglong2 bv = *(const ulonglong2*)&Wt[kk][4 * tx];
                #pragma unroll
                for (int i = 0; i < 4; i++) {
                    float a = (q == 0) ? av[i].x : (q == 1) ? av[i].y
                            : (q == 2) ? av[i].z : av[i].w;
                    ull aa = pack2(a, a);
                    fma2(acc[i][0], aa, bv.x);
                    fma2(acc[i][1], aa, bv.y);
                }
            }
        }
    }
    {
        const int d0 = 4 * tx;
        float4 xb = *(const float4*)&Xb[m * NDS + d0];
        float4 hb = *(const float4*)&Hb[m * NDS + d0];
        #pragma unroll
        for (int i = 0; i < 4; i++) {
            float2 lo = unpack2(acc[i][0]);
            float2 hi = unpack2(acc[i][1]);
            float4 v;
            v.x = lo.x + xb.x + hb.x;
            v.y = lo.y + xb.y + hb.y;
            v.z = hi.x + xb.z + hb.z;
            v.w = hi.y + xb.w + hb.w;
            *(float4*)&g_xp[((size_t)(bb * NS) + t0 + ty + 16 * i) * (NM * NDS) + m * NDS + d0] = v;
        }
    }
}

// ======================= Kernel 2: the sequential scan =====================
// R12 skeleton (best known: 384 threads, 3 syncs, weights in regs), with:
//   - rcp.approx for silu sigmoid and softmax denominator (chain cut)
//   - g_hn store of step t-1 done by idle warps 9-11 during the zW2 stage
__global__ void __launch_bounds__(384, 1) scan_kernel(
    const float* __restrict__ W1, const float* __restrict__ b1,
    const float* __restrict__ W2, const float* __restrict__ b2,
    const float* __restrict__ HW, const float* __restrict__ CW)
{
    __shared__ __align__(16) float sh_h[2][NM][NDS];  // double-buffered state
    __shared__ float sh_part[6][NDS];
    __shared__ float sh_raw[12];

    const int u  = threadIdx.x;
    const int bb = blockIdx.x;
    const int lane = u & 31;
    const int wp   = u >> 5;          // warp id 0..11

    // phase-1 mapping: output o1 (0..63), hc segment seg (0..5) of 32 elems
    const int o1  = u & 63;
    const int seg = u >> 6;
    // phase-4 mapping: output o2 = m*64+d (0..191), dot-half (0/1)
    const int half = u & 1;
    const int o2   = u >> 1;
    const int m4   = o2 >> 6;
    const int d4   = o2 & 63;
    const int s1 = (m4 == 0) ? 1 : 0;
    const int s2 = (m4 == 2) ? 1 : 2;
    const int src = half ? s2 : s1;

    // ---- weights into registers (packed f32 pairs) — R12 layout ----
    ull w1r[16];
    #pragma unroll
    for (int j = 0; j < 16; j++)
        w1r[j] = *(const ull*)(W1 + o1 * (NM * NDS) + seg * 32 + 2 * j);

    ull whw[16];   // HW[m4][d4][half*32 .. half*32+32)
    #pragma unroll
    for (int j = 0; j < 16; j++)
        whw[j] = *(const ull*)(HW + ((size_t)(m4 * NDS + d4)) * NDS + half * 32 + 2 * j);

    ull wcw[32];   // CW[m4][src][d4][0..64)
    #pragma unroll
    for (int j = 0; j < 32; j++)
        wcw[j] = *(const ull*)(CW + ((size_t)((m4 * NM + src) * NDS + d4)) * NDS + 2 * j);

    // gating constants (small): lane owns z[2*lane..2*lane+1]
    const float2 b1r = *(const float2*)(b1 + 2 * lane);
    ull w2l = 0;                      // W2[wp][2*lane..2*lane+1] for warps 0..8
    float b2p = 0.0f;
    if (wp < 9) {
        w2l = *(const ull*)(W2 + (size_t)wp * NDS + 2 * lane);
        b2p = b2[wp];
    }
    // flusher mapping (warps 9..11, 96 threads): each stores 2 h values of
    // the PREVIOUS step from sh_h to g_hn during the zW2 stage.
    const int fl = u - 288;           // 0..95 for warps 9..11

    if (u < NM * NDS) (&sh_h[0][0][0])[u] = 0.0f;
    __syncthreads();

    const float* xp_base = g_xp + (size_t)bb * NS * (NM * NDS);
    float* hn_blk = g_hn + (size_t)bb * NS * (NM * NDS);
    float xp_c = __ldg(xp_base + o2);      // t = 0

    for (int t = 0; t < NS; t++) {
        const int cur = t & 1, nxt = cur ^ 1;
        const int tn = (t + 1 < NS) ? (t + 1) : t;
        float xp_n = __ldg(xp_base + (size_t)tn * (NM * NDS) + o2);  // prefetch

        // ---- phase 1: z-partials: W1 row o1, segment seg of hc ----
        const float* hseg = &sh_h[cur][0][0] + seg * 32;
        ull a1 = 0, a2 = 0;
        #pragma unroll
        for (int j = 0; j < 8; j++) {
            ulonglong2 hv = *(const ulonglong2*)(hseg + 4 * j);
            fma2(a1, hv.x, w1r[2 * j]);
            fma2(a2, hv.y, w1r[2 * j + 1]);
        }
        sh_part[seg][o1] = sum2(a1) + sum2(a2);
        __syncthreads();

        // ---- zW2 stage: warps 0..8 gating; warps 9..11 flush h[t-1] ----
        if (wp < 9) {
            float2 zv = b1r;
            #pragma unroll
            for (int s = 0; s < 6; s++) {
                float2 pp = *(const float2*)&sh_part[s][2 * lane];
                zv.x += pp.x; zv.y += pp.y;
            }
            ull zp = pack2(tanh_fast(zv.x), tanh_fast(zv.y));
            ull q = 0; fma2(q, zp, w2l);
            float pr = sum2(q);
            #pragma unroll
            for (int off = 16; off; off >>= 1)
                pr += __shfl_down_sync(0xffffffffu, pr, off);
            if (lane == 0) sh_raw[wp] = pr + b2p;
        } else if (t > 0) {
            // flush previous step's h (sh_h[cur] holds h produced at t-1)
            float2 hv = *(const float2*)(&sh_h[cur][0][0] + 2 * fl);
            *(float2*)(hn_blk + (size_t)(t - 1) * (NM * NDS) + 2 * fl) = hv;
        }
        __syncthreads();

        // ---- phase 4: inline softmax + HW.h + coupling + xp; silu ----
        float r0 = sh_raw[m4 * 3 + 0];
        float r1 = sh_raw[m4 * 3 + 1];
        float r2 = sh_raw[m4 * 3 + 2];
        float e0 = __expf(r0), e1 = __expf(r1), e2 = __expf(r2);
        float inv = rcp_fast(e0 + e1 + e2);
        float esrc = (src == 0) ? e0 : ((src == 1) ? e1 : e2);
        float a = esrc * inv;          // masked row: src != m4 always

        const float* hm = &sh_h[cur][m4][0] + half * 32;
        const float* hs = &sh_h[cur][src][0];
        ull ah0 = 0, ah1 = 0, c0 = 0, c1 = 0, c2 = 0, c3 = 0;
        #pragma unroll
        for (int j = 0; j < 8; j++) {
            ulonglong2 hv = *(const ulonglong2*)(hm + 4 * j);
            fma2(ah0, hv.x, whw[2 * j]);
            fma2(ah1, hv.y, whw[2 * j + 1]);
        }
        #pragma unroll
        for (int j = 0; j < 16; j++) {
            ulonglong2 hv = *(const ulonglong2*)(hs + 4 * j);
            if (j & 1) { fma2(c2, hv.x, wcw[2 * j]); fma2(c3, hv.y, wcw[2 * j + 1]); }
            else       { fma2(c0, hv.x, wcw[2 * j]); fma2(c1, hv.y, wcw[2 * j + 1]); }
        }

        float val = sum2(ah0) + sum2(ah1)
                  + a * (sum2(c0) + sum2(c1) + sum2(c2) + sum2(c3));
        val += __shfl_xor_sync(0xffffffffu, val, 1);   // combine halves
        if (half == 0) {
            float su = val + xp_c;
            float hn = su * rcp_fast(1.0f + __expf(-su));   // silu via MUFU rcp
            sh_h[nxt][m4][d4] = hn;
        }
        xp_c = xp_n;
        __syncthreads();
    }
    // final flush: h of step NS-1 lives in sh_h[NS&1] = sh_h[0]
    if (wp >= 9) {
        float2 hv = *(const float2*)(&sh_h[NS & 1][0][0] + 2 * fl);
        *(float2*)(hn_blk + (size_t)(NS - 1) * (NM * NDS) + 2 * fl) = hv;
    }
}

// ======================= Kernel 3: y = OW@h_new + Ob; out = LN(y + x) ======
// vs baseline: dot uses FOUR accumulators (was one 128-cycle RAW chain).
__global__ void __launch_bounds__(256) out_kernel(
    const float* __restrict__ xa, const float* __restrict__ xv, const float* __restrict__ xl,
    const float* __restrict__ OW, const float* __restrict__ Ob,
    const float* __restrict__ lng, const float* __restrict__ lnb,
    float* __restrict__ out)
{
    __shared__ __align__(16) float sh_ht[2][8][NDS];
    __shared__ float sh_red[2][8][2];

    const int tid = threadIdx.x;
    const int t0  = blockIdx.x * TS;
    const int bb  = blockIdx.y;
    const int m   = blockIdx.z;
    const float* xm = (m == 0) ? xa : ((m == 1) ? xv : xl);

    ull ow[32];
    #pragma unroll
    for (int j = 0; j < 32; j++)
        ow[j] = *(const ull*)(OW + ((size_t)m * ND + tid) * NDS + 2 * j);
    const float ob = Ob[m * ND + tid];
    const float gg = lng[m * ND + tid];
    const float be = lnb[m * ND + tid];

    const float* hn_base = g_hn + ((size_t)(bb * NS + t0)) * (NM * NDS) + m * NDS;
    const float* x_base  = xm + ((size_t)bb * NS + t0) * ND;
    float* o_base = out + ((size_t)m * NB + bb) * (size_t)NS * ND + (size_t)t0 * ND;

    const int ptt = tid >> 4;
    const int pq  = tid & 15;

    if (tid < 128) {
        int tc = min(0 * 8 + ptt, TS - 1);
        cp_async16(&sh_ht[0][ptt][pq * 4], hn_base + (size_t)tc * (NM * NDS) + pq * 4);
    }
    cp_commit();

    const int NG = TS / 8;
    for (int g = 0; g < NG; g++) {
        const int buf = g & 1;
        if (tid < 128) {
            int tc = min((g + 1) * 8 + ptt, TS - 1);
            cp_async16(&sh_ht[buf ^ 1][ptt][pq * 4], hn_base + (size_t)tc * (NM * NDS) + pq * 4);
        }
        cp_commit();
        cp_wait1();
        __syncthreads();

        #pragma unroll
        for (int k = 0; k < 8; k++) {
            const int t = g * 8 + k;
            float xval = __ldg(x_base + (size_t)t * ND + tid);

            ull ac0 = 0, ac1 = 0, ac2 = 0, ac3 = 0;
            #pragma unroll
            for (int j = 0; j < 8; j++) {
                ulonglong2 h0 = *(const ulonglong2*)&sh_ht[buf][k][8 * j];
                ulonglong2 h1 = *(const ulonglong2*)&sh_ht[buf][k][8 * j + 4];
                fma2(ac0, h0.x, ow[4 * j + 0]);
                fma2(ac1, h0.y, ow[4 * j + 1]);
                fma2(ac2, h1.x, ow[4 * j + 2]);
                fma2(ac3, h1.y, ow[4 * j + 3]);
            }
            float v = sum2(ac0) + sum2(ac1) + sum2(ac2) + sum2(ac3) + ob + xval;

            float s = v, ss = v * v;
            #pragma unroll
            for (int off = 16; off; off >>= 1) {
                s  += __shfl_xor_sync(0xffffffffu, s, off);
                ss += __shfl_xor_sync(0xffffffffu, ss, off);
            }
            const int w = tid >> 5, lw = tid & 31;
            const int rb = t & 1;
            if (lw == 0) { sh_red[rb][w][0] = s; sh_red[rb][w][1] = ss; }
            __syncthreads();
            float S = 0.0f, SS = 0.0f;
            #pragma unroll
            for (int w2 = 0; w2 < 8; w2++) { S += sh_red[rb][w2][0]; SS += sh_red[rb][w2][1]; }
            float mu  = S * (1.0f / 256.0f);
            float var = SS * (1.0f / 256.0f) - mu * mu;
            float r   = rsqrtf(var + 1e-5f);
            o_base[(size_t)t * ND + tid] = (v - mu) * r * gg + be;
        }
    }
}

// =============================== launch ====================================
extern "C" void kernel_launch(void* const* d_in, const int* in_sizes, int n_in,
                              void* d_out, int out_size) {
    const float* xa  = (const float*)d_in[0];
    const float* xv  = (const float*)d_in[1];
    const float* xl  = (const float*)d_in[2];
    const float* XW  = (const float*)d_in[3];
    const float* Xb  = (const float*)d_in[4];
    const float* HW  = (const float*)d_in[5];
    const float* Hb  = (const float*)d_in[6];
    const float* OW  = (const float*)d_in[7];
    const float* Ob  = (const float*)d_in[8];
    const float* CW  = (const float*)d_in[9];
    const float* W1  = (const float*)d_in[10];
    const float* b1  = (const float*)d_in[11];
    const float* W2  = (const float*)d_in[12];
    const float* b2  = (const float*)d_in[13];
    const float* lng = (const float*)d_in[14];
    const float* lnb = (const float*)d_in[15];
    float* out = (float*)d_out;

    dim3 gA(NS / 64, NB, NM);
    xproj_kernel<<<gA, 256>>>(xa, xv, xl, XW, Xb, Hb);

    scan_kernel<<<NB, 384>>>(W1, b1, W2, b2, HW, CW);

    dim3 gC(NS / TS, NB, NM);
    out_kernel<<<gC, 256>>>(xa, xv, xl, OW, Ob, lng, lnb, out);
}